// round 12
// baseline (speedup 1.0000x reference)
#include <cuda_runtime.h>
#include <cuda_bf16.h>
#include <cstdint>

// out[n, d] = input[n, d] * W[d];  N=16384, D=4096, fp32.
// Pure stream: 256MB read-once + 256MB write-once.
//
// FINAL KERNEL — DRAM-roofline optimum.
// Session evidence (9 variants): bench pinned at 82.0±0.4us = 512MB /
// ~6.25TB/s sustained, invariant to occupancy (20-84%), access width
// (128/256-bit), cache policy, CTA->address mapping, and grid (512-32768;
// grid=512 persistent regressed -18% by starving request concurrency).
// SM issue ~5%: the chip waits on an irreducible byte count.
//
// Best-measured config:
//  - 256-bit accesses (LDG.E.256/STG.E.256) via ld/st.global.cs.v8.f32
//  - .cs streaming policy (no-reuse data, no L2 churn)
//  - R=4 chunks/thread, grid=8192, ~58 regs; CTA owns contiguous 32KB
//  - W resolved to 4 registers/thread (col = tid + (i&1)*256 trick)
// ncu: 73.6us, DRAM 82.4%, 6.53TB/s. Bench: 82.0us.

static constexpr int N_ROWS  = 16384;
static constexpr int D8      = 4096 / 8;            // 512 v8-chunks per row
static constexpr int THREADS = 256;
static constexpr int R       = 4;                   // v8 accesses per thread
static constexpr long long TOTAL8 = (long long)N_ROWS * D8;     // 8,388,608
static constexpr int GRID    = (int)(TOTAL8 / (THREADS * R));   // 8192

__global__ void __launch_bounds__(THREADS) diag_scale_final_kernel(
    const float* __restrict__ in,
    const float* __restrict__ w,
    float* __restrict__ out)
{
    // Chunk index = base + i*256. base % 512 == tid, so the D-column of
    // iteration i is tid + (i&1)*256: only two W v8-vectors per thread.
    unsigned base = blockIdx.x * (THREADS * R) + threadIdx.x;

    const float4* w4 = (const float4*)w;
    float4 we0 = __ldg(&w4[threadIdx.x * 2]);
    float4 we1 = __ldg(&w4[threadIdx.x * 2 + 1]);
    float4 wo0 = __ldg(&w4[(threadIdx.x + 256) * 2]);
    float4 wo1 = __ldg(&w4[(threadIdx.x + 256) * 2 + 1]);

    float a[R][8];
#pragma unroll
    for (int i = 0; i < R; i++) {
        const float* p = in + (size_t)(base + i * THREADS) * 8;
        asm volatile(
            "ld.global.cs.v8.f32 {%0,%1,%2,%3,%4,%5,%6,%7}, [%8];"
            : "=f"(a[i][0]), "=f"(a[i][1]), "=f"(a[i][2]), "=f"(a[i][3]),
              "=f"(a[i][4]), "=f"(a[i][5]), "=f"(a[i][6]), "=f"(a[i][7])
            : "l"(p));
    }

#pragma unroll
    for (int i = 0; i < R; i++) {
        float4 wl = (i & 1) ? wo0 : we0;
        float4 wh = (i & 1) ? wo1 : we1;
        float r0 = a[i][0] * wl.x, r1 = a[i][1] * wl.y;
        float r2 = a[i][2] * wl.z, r3 = a[i][3] * wl.w;
        float r4 = a[i][4] * wh.x, r5 = a[i][5] * wh.y;
        float r6 = a[i][6] * wh.z, r7 = a[i][7] * wh.w;
        float* p = out + (size_t)(base + i * THREADS) * 8;
        asm volatile(
            "st.global.cs.v8.f32 [%0], {%1,%2,%3,%4,%5,%6,%7,%8};"
            :: "l"(p),
               "f"(r0), "f"(r1), "f"(r2), "f"(r3),
               "f"(r4), "f"(r5), "f"(r6), "f"(r7)
            : "memory");
    }
}

extern "C" void kernel_launch(void* const* d_in, const int* in_sizes, int n_in,
                              void* d_out, int out_size) {
    const float* in = (const float*)d_in[0];
    const float* w  = (const float*)d_in[1];
    float* out = (float*)d_out;
    diag_scale_final_kernel<<<GRID, THREADS>>>(in, w, out);
}

// round 13
// speedup vs baseline: 1.0035x; 1.0035x over previous
#include <cuda_runtime.h>
#include <cuda_bf16.h>
#include <cstdint>

// out[n, d] = input[n, d] * W[d];  N=16384, D=4096, fp32.
// Pure stream: 256MB read-once + 256MB write-once.
//
// FINAL KERNEL — DRAM-roofline optimum (session converged).
// 10 consecutive benches at 82.0±0.4us = 512MB / ~6.25TB/s sustained,
// invariant to: occupancy (20-84%), access width (128/256-bit), cache
// policy (default/.cs), CTA->address mapping (4 layouts), grid size
// (2048-32768). Only deviation: grid=512 persistent regressed -18%
// (starved standing request concurrency). SM issue ~5% — the chip is
// bus-limited on an irreducible byte count.
//
// Config: 256-bit .cs loads/stores (LDG.E.256/STG.E.256), R=4 v8-chunks
// per thread, grid=8192 (oversubscribed), contiguous 32KB span per CTA,
// W resolved to 4 registers/thread via col = tid + (i&1)*256.
// ncu: 73.6-74.2us, DRAM 82%, ~6.5TB/s.

static constexpr int N_ROWS  = 16384;
static constexpr int D8      = 4096 / 8;            // 512 v8-chunks per row
static constexpr int THREADS = 256;
static constexpr int R       = 4;                   // v8 accesses per thread
static constexpr long long TOTAL8 = (long long)N_ROWS * D8;     // 8,388,608
static constexpr int GRID    = (int)(TOTAL8 / (THREADS * R));   // 8192

__global__ void __launch_bounds__(THREADS) diag_scale_final_kernel(
    const float* __restrict__ in,
    const float* __restrict__ w,
    float* __restrict__ out)
{
    // Chunk index = base + i*256. base % 512 == tid, so the D-column of
    // iteration i is tid + (i&1)*256: only two W v8-vectors per thread.
    unsigned base = blockIdx.x * (THREADS * R) + threadIdx.x;

    const float4* w4 = (const float4*)w;
    float4 we0 = __ldg(&w4[threadIdx.x * 2]);
    float4 we1 = __ldg(&w4[threadIdx.x * 2 + 1]);
    float4 wo0 = __ldg(&w4[(threadIdx.x + 256) * 2]);
    float4 wo1 = __ldg(&w4[(threadIdx.x + 256) * 2 + 1]);

    float a[R][8];
#pragma unroll
    for (int i = 0; i < R; i++) {
        const float* p = in + (size_t)(base + i * THREADS) * 8;
        asm volatile(
            "ld.global.cs.v8.f32 {%0,%1,%2,%3,%4,%5,%6,%7}, [%8];"
            : "=f"(a[i][0]), "=f"(a[i][1]), "=f"(a[i][2]), "=f"(a[i][3]),
              "=f"(a[i][4]), "=f"(a[i][5]), "=f"(a[i][6]), "=f"(a[i][7])
            : "l"(p));
    }

#pragma unroll
    for (int i = 0; i < R; i++) {
        float4 wl = (i & 1) ? wo0 : we0;
        float4 wh = (i & 1) ? wo1 : we1;
        float r0 = a[i][0] * wl.x, r1 = a[i][1] * wl.y;
        float r2 = a[i][2] * wl.z, r3 = a[i][3] * wl.w;
        float r4 = a[i][4] * wh.x, r5 = a[i][5] * wh.y;
        float r6 = a[i][6] * wh.z, r7 = a[i][7] * wh.w;
        float* p = out + (size_t)(base + i * THREADS) * 8;
        asm volatile(
            "st.global.cs.v8.f32 [%0], {%1,%2,%3,%4,%5,%6,%7,%8};"
            :: "l"(p),
               "f"(r0), "f"(r1), "f"(r2), "f"(r3),
               "f"(r4), "f"(r5), "f"(r6), "f"(r7)
            : "memory");
    }
}

extern "C" void kernel_launch(void* const* d_in, const int* in_sizes, int n_in,
                              void* d_out, int out_size) {
    const float* in = (const float*)d_in[0];
    const float* w  = (const float*)d_in[1];
    float* out = (float*)d_out;
    diag_scale_final_kernel<<<GRID, THREADS>>>(in, w, out);
}